// round 1
// baseline (speedup 1.0000x reference)
#include <cuda_runtime.h>
#include <cuda_bf16.h>

// Problem constants (fixed shapes per reference setup_inputs)
#define B_ 2
#define C_ 256
#define H_ 64
#define W_ 64
#define P_ (H_*W_)   // 4096
#define N_ 4
// Output channels per query: 4 levels * 81 window samples
#define K2_ 81
#define CTOT_ 324

// Pyramid scratch (device globals; allocation-free per harness rules)
__device__ float g_l0[(size_t)B_*P_*64*64];  // 128 MiB
__device__ float g_l1[(size_t)B_*P_*32*32];  //  32 MiB
__device__ float g_l2[(size_t)B_*P_*16*16];  //   8 MiB
__device__ float g_l3[(size_t)B_*P_*8*8];    //   2 MiB

// ---------------------------------------------------------------------------
// Kernel 1: all-pairs correlation  corr[b,p,q] = sum_c f1[b,c,p]*f2[b,c,q] / 16
// TN GEMM: A = f1 (K=256 x M=4096, row stride P), B = f2 (K x N), C = g_l0.
// 128x128 tile, BK=8, 256 threads, 8x8 per-thread microtile.
// ---------------------------------------------------------------------------
__global__ __launch_bounds__(256) void gemm_corr_kernel(
    const float* __restrict__ f1, const float* __restrict__ f2)
{
    __shared__ float As[8][128];
    __shared__ float Bs[8][128];

    const int b  = blockIdx.z;
    const int m0 = blockIdx.y * 128;
    const int n0 = blockIdx.x * 128;

    const float* A  = f1 + (size_t)b * C_ * P_;
    const float* Bp = f2 + (size_t)b * C_ * P_;

    const int tid = threadIdx.x;
    const int lkk = tid >> 5;          // 0..7  (K row for loads)
    const int lcc = (tid & 31) << 2;   // 0..124 (col, float4)
    const int tr  = tid >> 4;          // 0..15
    const int tc  = tid & 15;          // 0..15

    float acc[8][8];
    #pragma unroll
    for (int i = 0; i < 8; i++)
        #pragma unroll
        for (int j = 0; j < 8; j++) acc[i][j] = 0.0f;

    for (int k0 = 0; k0 < C_; k0 += 8) {
        float4 a4 = *(const float4*)(A  + (size_t)(k0 + lkk) * P_ + m0 + lcc);
        float4 b4 = *(const float4*)(Bp + (size_t)(k0 + lkk) * P_ + n0 + lcc);
        As[lkk][lcc+0] = a4.x; As[lkk][lcc+1] = a4.y;
        As[lkk][lcc+2] = a4.z; As[lkk][lcc+3] = a4.w;
        Bs[lkk][lcc+0] = b4.x; Bs[lkk][lcc+1] = b4.y;
        Bs[lkk][lcc+2] = b4.z; Bs[lkk][lcc+3] = b4.w;
        __syncthreads();

        #pragma unroll
        for (int kq = 0; kq < 8; kq++) {
            float ar[8], br[8];
            #pragma unroll
            for (int i = 0; i < 8; i++) ar[i] = As[kq][tr * 8 + i];
            #pragma unroll
            for (int j = 0; j < 8; j++) br[j] = Bs[kq][tc * 8 + j];
            #pragma unroll
            for (int i = 0; i < 8; i++)
                #pragma unroll
                for (int j = 0; j < 8; j++)
                    acc[i][j] += ar[i] * br[j];
        }
        __syncthreads();
    }

    // scale by 1/sqrt(C) = 1/16 and store
    #pragma unroll
    for (int i = 0; i < 8; i++) {
        size_t row = (size_t)(b * P_ + m0 + tr * 8 + i);
        float* dst = g_l0 + row * P_ + n0 + tc * 8;
        float4 v0 = make_float4(acc[i][0]*0.0625f, acc[i][1]*0.0625f,
                                acc[i][2]*0.0625f, acc[i][3]*0.0625f);
        float4 v1 = make_float4(acc[i][4]*0.0625f, acc[i][5]*0.0625f,
                                acc[i][6]*0.0625f, acc[i][7]*0.0625f);
        *(float4*)(dst)     = v0;
        *(float4*)(dst + 4) = v1;
    }
}

// ---------------------------------------------------------------------------
// Kernel 2: 2x2 average pooling, hierarchical. One thread per output element.
// Layout: ((bp)*h + y)*w + x where bp = b*P + p.
// ---------------------------------------------------------------------------
__global__ void pool_l1_kernel() {
    const int wi = 64, wo = 32;
    int idx = blockIdx.x * blockDim.x + threadIdx.x;
    const int total = B_ * P_ * wo * wo;
    if (idx >= total) return;
    int x  = idx % wo;
    int t  = idx / wo;
    int y  = t % wo;
    int bp = t / wo;
    const float* s = g_l0 + ((size_t)bp * wi + 2*y) * wi + 2*x;
    g_l1[idx] = 0.25f * (s[0] + s[1] + s[wi] + s[wi+1]);
}
__global__ void pool_l2_kernel() {
    const int wi = 32, wo = 16;
    int idx = blockIdx.x * blockDim.x + threadIdx.x;
    const int total = B_ * P_ * wo * wo;
    if (idx >= total) return;
    int x  = idx % wo;
    int t  = idx / wo;
    int y  = t % wo;
    int bp = t / wo;
    const float* s = g_l1 + ((size_t)bp * wi + 2*y) * wi + 2*x;
    g_l2[idx] = 0.25f * (s[0] + s[1] + s[wi] + s[wi+1]);
}
__global__ void pool_l3_kernel() {
    const int wi = 16, wo = 8;
    int idx = blockIdx.x * blockDim.x + threadIdx.x;
    const int total = B_ * P_ * wo * wo;
    if (idx >= total) return;
    int x  = idx % wo;
    int t  = idx / wo;
    int y  = t % wo;
    int bp = t / wo;
    const float* s = g_l2 + ((size_t)bp * wi + 2*y) * wi + 2*x;
    g_l3[idx] = 0.25f * (s[0] + s[1] + s[wi] + s[wi+1]);
}

// ---------------------------------------------------------------------------
// Kernel 3: window gather + bilinear.
// One warp per (b, n, p, level). Key: window offsets are integers, so
// floor/frac are shared by all 81 samples. Warp loads a zero-padded 10x10
// patch into shared, then each lane emits ~3 of the 81 outputs.
// k ordering faithful to reference: off_x = d[k/9], off_y = d[k%9].
// ---------------------------------------------------------------------------
__global__ __launch_bounds__(256) void gather_kernel(
    const float* __restrict__ coords, float* __restrict__ out)
{
    __shared__ float patch[8][104];   // 100 used, padded

    const int wl   = threadIdx.x >> 5;
    const int lane = threadIdx.x & 31;
    unsigned w = blockIdx.x * 8u + wl;   // 0 .. 131071

    const int l = w & 3;  w >>= 2;
    const int p = w & (P_ - 1); w >>= 12;
    const int n = w & 3;
    const int b = w >> 2;

    const float cx = coords[((size_t)((b * N_ + n) * 2 + 0)) * P_ + p];
    const float cy = coords[((size_t)((b * N_ + n) * 2 + 1)) * P_ + p];

    const float inv = 1.0f / (float)(1 << l);   // exact power of two
    const float xs = cx * inv;
    const float ys = cy * inv;
    const float x0f = floorf(xs);
    const float y0f = floorf(ys);
    const float fx = xs - x0f;
    const float fy = ys - y0f;
    const int x0 = (int)x0f;
    const int y0 = (int)y0f;
    const int sz = 64 >> l;

    const float* base;
    switch (l) {
        case 0:  base = g_l0; break;
        case 1:  base = g_l1; break;
        case 2:  base = g_l2; break;
        default: base = g_l3; break;
    }
    base += (size_t)(b * P_ + p) * sz * sz;

    // Load 10x10 zero-padded patch: patch[j*10+i] = corr(y0-4+j, x0-4+i)
    #pragma unroll
    for (int t = lane; t < 100; t += 32) {
        int j = t / 10, i = t % 10;
        int yy = y0 - 4 + j;
        int xx = x0 - 4 + i;
        float v = 0.0f;
        if ((unsigned)yy < (unsigned)sz && (unsigned)xx < (unsigned)sz)
            v = base[yy * sz + xx];
        patch[wl][t] = v;
    }
    __syncwarp();

    const float w00 = (1.0f - fy) * (1.0f - fx);
    const float w01 = (1.0f - fy) * fx;
    const float w10 = fy * (1.0f - fx);
    const float w11 = fy * fx;

    float* ob = out + ((size_t)((b * N_ + n) * P_ + p)) * CTOT_ + l * K2_;

    #pragma unroll
    for (int k = lane; k < K2_; k += 32) {
        int ix = k / 9;   // x offset index (outer, per reference meshgrid swap)
        int iy = k % 9;   // y offset index (inner)
        float v00 = patch[wl][iy * 10 + ix];
        float v01 = patch[wl][iy * 10 + ix + 1];
        float v10 = patch[wl][(iy + 1) * 10 + ix];
        float v11 = patch[wl][(iy + 1) * 10 + ix + 1];
        ob[k] = w00 * v00 + w01 * v01 + w10 * v10 + w11 * v11;
    }
}

// ---------------------------------------------------------------------------
extern "C" void kernel_launch(void* const* d_in, const int* in_sizes, int n_in,
                              void* d_out, int out_size)
{
    const float* f1     = (const float*)d_in[0];
    const float* f2     = (const float*)d_in[1];
    const float* coords = (const float*)d_in[2];
    float* out = (float*)d_out;

    // 1) all-pairs correlation -> g_l0
    dim3 gg(P_ / 128, P_ / 128, B_);   // 32 x 32 x 2
    gemm_corr_kernel<<<gg, 256>>>(f1, f2);

    // 2) pyramid
    {
        int total1 = B_ * P_ * 32 * 32;
        pool_l1_kernel<<<(total1 + 255) / 256, 256>>>();
        int total2 = B_ * P_ * 16 * 16;
        pool_l2_kernel<<<(total2 + 255) / 256, 256>>>();
        int total3 = B_ * P_ * 8 * 8;
        pool_l3_kernel<<<(total3 + 255) / 256, 256>>>();
    }

    // 3) gather: B*N*P*L = 131072 warps, 8 warps/block -> 16384 blocks
    gather_kernel<<<(B_ * N_ * P_ * 4) / 8, 256>>>(coords, out);
}

// round 4
// speedup vs baseline: 2.0996x; 2.0996x over previous
#include <cuda_runtime.h>
#include <cuda_bf16.h>
#include <cstdint>

// Problem constants
#define B_ 2
#define C_ 256
#define H_ 64
#define W_ 64
#define P_ 4096
#define N_ 4
#define K2_ 81
#define CTOT_ 324

// ---------------------------------------------------------------------------
// Device scratch (allocation-free per harness rules)
// ---------------------------------------------------------------------------
__device__ float g_l0[(size_t)B_*P_*64*64];  // 128 MiB
__device__ float g_l1[(size_t)B_*P_*32*32];  //  32 MiB
__device__ float g_l2[(size_t)B_*P_*16*16];  //   8 MiB
__device__ float g_l3[(size_t)B_*P_*8*8];    //   2 MiB

// bf16 split operands, layout [b][c][p] (same as inputs)
__device__ __nv_bfloat16 gA_hi[(size_t)B_*C_*P_];
__device__ __nv_bfloat16 gA_lo[(size_t)B_*C_*P_];
__device__ __nv_bfloat16 gB_hi[(size_t)B_*C_*P_];
__device__ __nv_bfloat16 gB_lo[(size_t)B_*C_*P_];

// ---------------------------------------------------------------------------
// PTX helpers (base sm_80-class features only; no arch-variant instructions)
// ---------------------------------------------------------------------------
__device__ __forceinline__ uint32_t smem_u32(const void* p) {
    uint32_t a;
    asm("{ .reg .u64 t; cvta.to.shared.u64 t, %1; cvt.u32.u64 %0, t; }" : "=r"(a) : "l"(p));
    return a;
}
__device__ __forceinline__ void cp16(uint32_t d, const void* s) {
    asm volatile("cp.async.cg.shared.global [%0], [%1], 16;" :: "r"(d), "l"(s));
}
__device__ __forceinline__ void cp_commit() {
    asm volatile("cp.async.commit_group;" ::: "memory");
}
__device__ __forceinline__ void ldsm4t(uint32_t* r, uint32_t a) {
    asm volatile("ldmatrix.sync.aligned.m8n8.x4.trans.shared.b16 {%0,%1,%2,%3}, [%4];"
        : "=r"(r[0]), "=r"(r[1]), "=r"(r[2]), "=r"(r[3]) : "r"(a));
}
__device__ __forceinline__ void ldsm2t(uint32_t* r, uint32_t a) {
    asm volatile("ldmatrix.sync.aligned.m8n8.x2.trans.shared.b16 {%0,%1}, [%2];"
        : "=r"(r[0]), "=r"(r[1]) : "r"(a));
}
__device__ __forceinline__ void mma16816(float* c, const uint32_t* a, const uint32_t* b) {
    asm volatile("mma.sync.aligned.m16n8k16.row.col.f32.bf16.bf16.f32 "
        "{%0,%1,%2,%3}, {%4,%5,%6,%7}, {%8,%9}, {%0,%1,%2,%3};"
        : "+f"(c[0]), "+f"(c[1]), "+f"(c[2]), "+f"(c[3])
        : "r"(a[0]), "r"(a[1]), "r"(a[2]), "r"(a[3]), "r"(b[0]), "r"(b[1]));
}

// XOR swizzle of 16B group index g within a 256B k-row (bank period 128B = 8 groups)
#define SWZ(g, k) (((g) & 8) | (((g) ^ (k)) & 7))

// ---------------------------------------------------------------------------
// Kernel 0: fp32 -> (bf16 hi, bf16 lo), elementwise, layout preserved.
// which = 0 -> gA_*, which = 1 -> gB_*  (device globals referenced IN DEVICE
// CODE — passing them as host-side kernel args aliases the host shadow symbol
// and silently writes host memory via ATS; that was the round-3 bug).
// ---------------------------------------------------------------------------
__global__ __launch_bounds__(256) void convert_kernel(
    const float* __restrict__ src, int which)
{
    __nv_bfloat16* __restrict__ dhi = which ? gB_hi : gA_hi;
    __nv_bfloat16* __restrict__ dlo = which ? gB_lo : gA_lo;

    size_t i = ((size_t)blockIdx.x * 256 + threadIdx.x) * 4;
    float4 v = *(const float4*)(src + i);
    float xs[4] = {v.x, v.y, v.z, v.w};
    uint32_t hu[4], lu[4];
    #pragma unroll
    for (int k = 0; k < 4; k++) {
        __nv_bfloat16 h = __float2bfloat16(xs[k]);
        float r = xs[k] - __bfloat162float(h);
        __nv_bfloat16 l = __float2bfloat16(r);
        hu[k] = (uint32_t)__bfloat16_as_ushort(h);
        lu[k] = (uint32_t)__bfloat16_as_ushort(l);
    }
    uint2 hp = make_uint2(hu[0] | (hu[1] << 16), hu[2] | (hu[3] << 16));
    uint2 lp = make_uint2(lu[0] | (lu[1] << 16), lu[2] | (lu[3] << 16));
    *(uint2*)((unsigned char*)dhi + i * 2) = hp;
    *(uint2*)((unsigned char*)dlo + i * 2) = lp;
}

// ---------------------------------------------------------------------------
// Kernel 1: HMMA (mma.sync) correlation GEMM + fused pool_l1.
// Block tile 128(m) x 128(n), K=256 in 16 chunks of 16, 3-term bf16 split.
// 8 warps = 4(m) x 2(n); warp tile 32x64. Double-buffered cp.async.
// Smem stage (16KB): Ahi | Alo | Bhi | Blo, each 16 k-rows x 256B, swizzled.
// ---------------------------------------------------------------------------
__global__ __launch_bounds__(256, 2) void gemm_hmma_kernel()
{
    __shared__ __align__(1024) unsigned char smem[32768];
    const uint32_t sbase = smem_u32(smem);

    const int tid  = threadIdx.x;
    const int lane = tid & 31;
    const int wid  = tid >> 5;
    const int nt = blockIdx.x, mt = blockIdx.y, b = blockIdx.z;
    const int warp_m = wid & 3, warp_n = wid >> 2;
    const int m0w = warp_m * 32, n0w = warp_n * 64;

    // --- cp.async mapping: thread -> (k row, 16B group) ---
    const int ck = tid >> 4;        // 0..15
    const int cg = tid & 15;        // 0..15
    const uint32_t cdst = ck * 256 + SWZ(cg, ck) * 16;
    const size_t gsrc_a = ((size_t)b * C_ + ck) * P_ + mt * 128 + cg * 8;
    const size_t gsrc_b = ((size_t)b * C_ + ck) * P_ + nt * 128 + cg * 8;

    auto prefetch = [&](int s, int c) {
        uint32_t st = sbase + s * 16384 + cdst;
        size_t koff = (size_t)c * 16 * P_;
        cp16(st +     0, gA_hi + gsrc_a + koff);
        cp16(st +  4096, gA_lo + gsrc_a + koff);
        cp16(st +  8192, gB_hi + gsrc_b + koff);
        cp16(st + 12288, gB_lo + gsrc_b + koff);
        cp_commit();
    };

    // --- ldmatrix lane addressing ---
    const int alk   = (lane & 7) | ((lane & 16) >> 1); // A: k row
    const int amsel = (lane >> 3) & 1;                 // A: m-group select
    const int blk   = lane & 15;                       // B: k row

    float acc[2][8][4];
    #pragma unroll
    for (int i = 0; i < 2; i++)
        #pragma unroll
        for (int j = 0; j < 8; j++)
            #pragma unroll
            for (int q = 0; q < 4; q++) acc[i][j][q] = 0.0f;

    prefetch(0, 0);
    prefetch(1, 1);

    for (int c = 0; c < 16; c++) {
        if (c == 15) asm volatile("cp.async.wait_group 0;" ::: "memory");
        else         asm volatile("cp.async.wait_group 1;" ::: "memory");
        __syncthreads();

        uint32_t st = sbase + (c & 1) * 16384;

        uint32_t ah[2][4], al[2][4];
        #pragma unroll
        for (int i = 0; i < 2; i++) {
            int mg = (m0w >> 3) + i * 2 + amsel;
            uint32_t addr = st + alk * 256 + SWZ(mg, alk) * 16;
            ldsm4t(ah[i], addr);
            ldsm4t(al[i], addr + 4096);
        }

        #pragma unroll
        for (int jh = 0; jh < 2; jh++) {
            uint32_t bh[4][2], bl[4][2];
            #pragma unroll
            for (int j4 = 0; j4 < 4; j4++) {
                int j = jh * 4 + j4;
                int ng = (n0w >> 3) + j;
                uint32_t addr = st + 8192 + blk * 256 + SWZ(ng, blk) * 16;
                ldsm2t(bh[j4], addr);
                ldsm2t(bl[j4], addr + 4096);
            }
            #pragma unroll
            for (int i = 0; i < 2; i++)
                #pragma unroll
                for (int j4 = 0; j4 < 4; j4++) {
                    int j = jh * 4 + j4;
                    mma16816(acc[i][j], ah[i], bh[j4]);
                    mma16816(acc[i][j], ah[i], bl[j4]);
                    mma16816(acc[i][j], al[i], bh[j4]);
                }
        }

        __syncthreads();
        if (c + 2 < 16) prefetch(c & 1, c + 2);
    }

    // --- epilogue: scale, store l0, fused pool_l1 ---
    #pragma unroll
    for (int i = 0; i < 2; i++)
        #pragma unroll
        for (int j = 0; j < 8; j++)
            #pragma unroll
            for (int q = 0; q < 4; q++) acc[i][j][q] *= 0.0625f;

    const int qr = lane >> 2;     // 0..7
    const int qc = lane & 3;      // 0..3

    // l0 stores (float2 per fragment reg pair)
    #pragma unroll
    for (int i = 0; i < 2; i++) {
        int m = mt * 128 + m0w + i * 16 + qr;
        size_t row0 = ((size_t)(b * P_ + m)) * P_;
        size_t row1 = ((size_t)(b * P_ + m + 8)) * P_;
        #pragma unroll
        for (int j = 0; j < 8; j++) {
            int nn = nt * 128 + n0w + j * 8 + qc * 2;
            *(float2*)(g_l0 + row0 + nn) = make_float2(acc[i][j][0], acc[i][j][1]);
            *(float2*)(g_l0 + row1 + nn) = make_float2(acc[i][j][2], acc[i][j][3]);
        }
    }

    // pool_l1: the n-tile (128 cols) = image rows y=2nt (warp_n=0 cols) and
    // y=2nt+1 (warp_n=1 cols) -> one l1 row (y'=nt) of 32 x-pixels.
    __syncthreads();                 // operand stages dead; alias as l1 buffer
    float* l1buf = (float*)smem;     // [128][33]
    if (warp_n == 0) {
        #pragma unroll
        for (int i = 0; i < 2; i++) {
            int mr = m0w + i * 16 + qr;
            #pragma unroll
            for (int j = 0; j < 8; j++) {
                int xp = j * 4 + qc;
                l1buf[mr * 33 + xp]       = acc[i][j][0] + acc[i][j][1];
                l1buf[(mr + 8) * 33 + xp] = acc[i][j][2] + acc[i][j][3];
            }
        }
    }
    __syncthreads();
    if (warp_n == 1) {
        #pragma unroll
        for (int i = 0; i < 2; i++) {
            int mr = m0w + i * 16 + qr;
            #pragma unroll
            for (int j = 0; j < 8; j++) {
                int xp = j * 4 + qc;
                l1buf[mr * 33 + xp]       += acc[i][j][0] + acc[i][j][1];
                l1buf[(mr + 8) * 33 + xp] += acc[i][j][2] + acc[i][j][3];
            }
        }
    }
    __syncthreads();
    {
        int m = tid >> 1, half = tid & 1;
        const float* sp = l1buf + m * 33 + half * 16;
        float* dst = g_l1 + ((size_t)(b * P_ + mt * 128 + m)) * 1024 + nt * 32 + half * 16;
        #pragma unroll
        for (int q = 0; q < 16; q++) dst[q] = sp[q] * 0.25f;
    }
}

// ---------------------------------------------------------------------------
// Kernel 2: pooling l1->l2->l3
// ---------------------------------------------------------------------------
__global__ void pool_l2_kernel() {
    const int wi = 32, wo = 16;
    int idx = blockIdx.x * blockDim.x + threadIdx.x;
    const int total = B_ * P_ * wo * wo;
    if (idx >= total) return;
    int x  = idx % wo;
    int t  = idx / wo;
    int y  = t % wo;
    int bp = t / wo;
    const float* s = g_l1 + ((size_t)bp * wi + 2*y) * wi + 2*x;
    g_l2[idx] = 0.25f * (s[0] + s[1] + s[wi] + s[wi+1]);
}
__global__ void pool_l3_kernel() {
    const int wi = 16, wo = 8;
    int idx = blockIdx.x * blockDim.x + threadIdx.x;
    const int total = B_ * P_ * wo * wo;
    if (idx >= total) return;
    int x  = idx % wo;
    int t  = idx / wo;
    int y  = t % wo;
    int bp = t / wo;
    const float* s = g_l2 + ((size_t)bp * wi + 2*y) * wi + 2*x;
    g_l3[idx] = 0.25f * (s[0] + s[1] + s[wi] + s[wi+1]);
}

// ---------------------------------------------------------------------------
// Kernel 3: window gather + bilinear
// ---------------------------------------------------------------------------
__global__ __launch_bounds__(256) void gather_kernel(
    const float* __restrict__ coords, float* __restrict__ out)
{
    __shared__ float patch[8][104];

    const int wl   = threadIdx.x >> 5;
    const int lane = threadIdx.x & 31;
    unsigned w = blockIdx.x * 8u + wl;

    const int l = w & 3;  w >>= 2;
    const int p = w & (P_ - 1); w >>= 12;
    const int n = w & 3;
    const int b = w >> 2;

    const float cx = coords[((size_t)((b * N_ + n) * 2 + 0)) * P_ + p];
    const float cy = coords[((size_t)((b * N_ + n) * 2 + 1)) * P_ + p];

    const float inv = 1.0f / (float)(1 << l);
    const float xs = cx * inv;
    const float ys = cy * inv;
    const float x0f = floorf(xs);
    const float y0f = floorf(ys);
    const float fx = xs - x0f;
    const float fy = ys - y0f;
    const int x0 = (int)x0f;
    const int y0 = (int)y0f;
    const int sz = 64 >> l;

    const float* base;
    switch (l) {
        case 0:  base = g_l0; break;
        case 1:  base = g_l1; break;
        case 2:  base = g_l2; break;
        default: base = g_l3; break;
    }
    base += (size_t)(b * P_ + p) * sz * sz;

    #pragma unroll
    for (int t = lane; t < 100; t += 32) {
        int j = t / 10, i = t % 10;
        int yy = y0 - 4 + j;
        int xx = x0 - 4 + i;
        float v = 0.0f;
        if ((unsigned)yy < (unsigned)sz && (unsigned)xx < (unsigned)sz)
            v = base[yy * sz + xx];
        patch[wl][t] = v;
    }
    __syncwarp();

    const float w00 = (1.0f - fy) * (1.0f - fx);
    const float w01 = (1.0f - fy) * fx;
    const float w10 = fy * (1.0f - fx);
    const float w11 = fy * fx;

    float* ob = out + ((size_t)((b * N_ + n) * P_ + p)) * CTOT_ + l * K2_;

    #pragma unroll
    for (int k = lane; k < K2_; k += 32) {
        int ix = k / 9;
        int iy = k % 9;
        float v00 = patch[wl][iy * 10 + ix];
        float v01 = patch[wl][iy * 10 + ix + 1];
        float v10 = patch[wl][(iy + 1) * 10 + ix];
        float v11 = patch[wl][(iy + 1) * 10 + ix + 1];
        ob[k] = w00 * v00 + w01 * v01 + w10 * v10 + w11 * v11;
    }
}

// ---------------------------------------------------------------------------
extern "C" void kernel_launch(void* const* d_in, const int* in_sizes, int n_in,
                              void* d_out, int out_size)
{
    const float* f1     = (const float*)d_in[0];
    const float* f2     = (const float*)d_in[1];
    const float* coords = (const float*)d_in[2];
    float* out = (float*)d_out;

    // 0) bf16 split (elementwise, layout preserved); selector picks dest globals
    int cgrid = (B_ * C_ * P_) / (256 * 4);   // 2048
    convert_kernel<<<cgrid, 256>>>(f1, 0);
    convert_kernel<<<cgrid, 256>>>(f2, 1);

    // 1) HMMA correlation GEMM (+ fused pool_l1)
    dim3 gg(32, 32, 2);
    gemm_hmma_kernel<<<gg, 256>>>();

    // 2) pyramid tail
    {
        int total2 = B_ * P_ * 16 * 16;
        pool_l2_kernel<<<(total2 + 255) / 256, 256>>>();
        int total3 = B_ * P_ * 8 * 8;
        pool_l3_kernel<<<(total3 + 255) / 256, 256>>>();
    }

    // 3) gather
    gather_kernel<<<(B_ * N_ * P_ * 4) / 8, 256>>>(coords, out);
}

// round 6
// speedup vs baseline: 2.2085x; 1.0519x over previous
#include <cuda_runtime.h>
#include <cuda_bf16.h>
#include <cstdint>

// Problem constants
#define B_ 2
#define C_ 256
#define H_ 64
#define W_ 64
#define P_ 4096
#define N_ 4
#define K2_ 81
#define CTOT_ 324

// ---------------------------------------------------------------------------
// Device scratch (allocation-free per harness rules)
// ---------------------------------------------------------------------------
__device__ float g_l0[(size_t)B_*P_*64*64];  // 128 MiB
__device__ float g_l1[(size_t)B_*P_*32*32];  //  32 MiB
__device__ float g_l2[(size_t)B_*P_*16*16];  //   8 MiB
__device__ float g_l3[(size_t)B_*P_*8*8];    //   2 MiB

// bf16 split operands, layout [b][c][p] (same as inputs)
__device__ __nv_bfloat16 gA_hi[(size_t)B_*C_*P_];
__device__ __nv_bfloat16 gA_lo[(size_t)B_*C_*P_];
__device__ __nv_bfloat16 gB_hi[(size_t)B_*C_*P_];
__device__ __nv_bfloat16 gB_lo[(size_t)B_*C_*P_];

// ---------------------------------------------------------------------------
// PTX helpers (base sm_80-class features only)
// ---------------------------------------------------------------------------
__device__ __forceinline__ uint32_t smem_u32(const void* p) {
    uint32_t a;
    asm("{ .reg .u64 t; cvta.to.shared.u64 t, %1; cvt.u32.u64 %0, t; }" : "=r"(a) : "l"(p));
    return a;
}
__device__ __forceinline__ void cp16(uint32_t d, const void* s) {
    asm volatile("cp.async.cg.shared.global [%0], [%1], 16;" :: "r"(d), "l"(s));
}
__device__ __forceinline__ void cp_commit() {
    asm volatile("cp.async.commit_group;" ::: "memory");
}
__device__ __forceinline__ void ldsm4t(uint32_t* r, uint32_t a) {
    asm volatile("ldmatrix.sync.aligned.m8n8.x4.trans.shared.b16 {%0,%1,%2,%3}, [%4];"
        : "=r"(r[0]), "=r"(r[1]), "=r"(r[2]), "=r"(r[3]) : "r"(a));
}
__device__ __forceinline__ void mma16816(float* c, const uint32_t* a, const uint32_t* b) {
    asm volatile("mma.sync.aligned.m16n8k16.row.col.f32.bf16.bf16.f32 "
        "{%0,%1,%2,%3}, {%4,%5,%6,%7}, {%8,%9}, {%0,%1,%2,%3};"
        : "+f"(c[0]), "+f"(c[1]), "+f"(c[2]), "+f"(c[3])
        : "r"(a[0]), "r"(a[1]), "r"(a[2]), "r"(a[3]), "r"(b[0]), "r"(b[1]));
}

// XOR swizzle of 16B group index g within a 256B k-row (bank period 128B = 8 groups)
#define SWZ(g, k) (((g) & 8) | (((g) ^ (k)) & 7))

// ---------------------------------------------------------------------------
// Kernel 0: fp32 -> (bf16 hi, bf16 lo), both tensors in one launch.
// blockIdx.y selects (f1 -> gA_*) vs (f2 -> gB_*). Device globals referenced
// in device code only (host-side shadow symbols alias host memory via ATS).
// ---------------------------------------------------------------------------
__global__ __launch_bounds__(256) void convert_kernel(
    const float* __restrict__ f1, const float* __restrict__ f2)
{
    const int which = blockIdx.y;
    const float* __restrict__ src = which ? f2 : f1;
    __nv_bfloat16* __restrict__ dhi = which ? gB_hi : gA_hi;
    __nv_bfloat16* __restrict__ dlo = which ? gB_lo : gA_lo;

    size_t i = ((size_t)blockIdx.x * 256 + threadIdx.x) * 4;
    float4 v = *(const float4*)(src + i);
    float xs[4] = {v.x, v.y, v.z, v.w};
    uint32_t hu[4], lu[4];
    #pragma unroll
    for (int k = 0; k < 4; k++) {
        __nv_bfloat16 h = __float2bfloat16(xs[k]);
        float r = xs[k] - __bfloat162float(h);
        __nv_bfloat16 l = __float2bfloat16(r);
        hu[k] = (uint32_t)__bfloat16_as_ushort(h);
        lu[k] = (uint32_t)__bfloat16_as_ushort(l);
    }
    uint2 hp = make_uint2(hu[0] | (hu[1] << 16), hu[2] | (hu[3] << 16));
    uint2 lp = make_uint2(lu[0] | (lu[1] << 16), lu[2] | (lu[3] << 16));
    *(uint2*)((unsigned char*)dhi + i * 2) = hp;
    *(uint2*)((unsigned char*)dlo + i * 2) = lp;
}

// ---------------------------------------------------------------------------
// Kernel 1: HMMA correlation GEMM + fused pool_l1.
// Block tile 128x128, K=256 in 16 chunks of 16, 3-term bf16 split.
// 8 warps = 4(m) x 2(n); warp tile 32x64. THREE-stage cp.async pipeline,
// ONE __syncthreads per chunk. B fragments via ldmatrix.x4 (2 n-groups/op).
// Stage (16KB): Ahi | Alo | Bhi | Blo, each 16 k-rows x 256B, swizzled.
// ---------------------------------------------------------------------------
__global__ __launch_bounds__(256, 2) void gemm_hmma_kernel()
{
    __shared__ __align__(1024) unsigned char smem[49152];   // 3 x 16KB stages
    const uint32_t sbase = smem_u32(smem);

    const int tid  = threadIdx.x;
    const int lane = tid & 31;
    const int wid  = tid >> 5;
    const int nt = blockIdx.x, mt = blockIdx.y, b = blockIdx.z;
    const int warp_m = wid & 3, warp_n = wid >> 2;
    const int m0w = warp_m * 32, n0w = warp_n * 64;

    // --- cp.async mapping: thread -> (k row, 16B group) ---
    const int ck = tid >> 4;        // 0..15
    const int cg = tid & 15;        // 0..15
    const uint32_t cdst = ck * 256 + SWZ(cg, ck) * 16;
    const size_t gsrc_a = ((size_t)b * C_ + ck) * P_ + mt * 128 + cg * 8;
    const size_t gsrc_b = ((size_t)b * C_ + ck) * P_ + nt * 128 + cg * 8;

    auto prefetch = [&](int s, int c) {
        uint32_t st = sbase + s * 16384 + cdst;
        size_t koff = (size_t)c * 16 * P_;
        cp16(st +     0, gA_hi + gsrc_a + koff);
        cp16(st +  4096, gA_lo + gsrc_a + koff);
        cp16(st +  8192, gB_hi + gsrc_b + koff);
        cp16(st + 12288, gB_lo + gsrc_b + koff);
        cp_commit();
    };

    // --- ldmatrix lane addressing ---
    // A (x4): lanes 0-7 -> mg rows k0-7? No: A trans x4 loads 4 8x8 matrices
    // covering m16 x k16 of one 16-row m-pair; per-lane k row + m-group select.
    const int alk   = (lane & 7) | ((lane & 16) >> 1); // A: k row 0..15
    const int amsel = (lane >> 3) & 1;                 // A: m-group select
    // B (x4): matrix idx mm = lane>>3: mm&1 -> k half, mm>>1 -> n-group pair member
    const int bkrow = (lane & 7) | ((lane & 8));       // k row 0..15
    const int bngo  = (lane >> 4) & 1;                 // +0 / +1 n-group

    float acc[2][8][4];
    #pragma unroll
    for (int i = 0; i < 2; i++)
        #pragma unroll
        for (int j = 0; j < 8; j++)
            #pragma unroll
            for (int q = 0; q < 4; q++) acc[i][j][q] = 0.0f;

    prefetch(0, 0);
    prefetch(1, 1);

    for (int c = 0; c < 16; c++) {
        if (c < 14) asm volatile("cp.async.wait_group 1;" ::: "memory");
        else        asm volatile("cp.async.wait_group 0;" ::: "memory");
        __syncthreads();
        if (c + 2 < 16) prefetch((c + 2) % 3, c + 2);

        uint32_t st = sbase + (c % 3) * 16384;

        uint32_t ah[2][4], al[2][4];
        #pragma unroll
        for (int i = 0; i < 2; i++) {
            int mg = (m0w >> 3) + i * 2 + amsel;
            uint32_t addr = st + alk * 256 + SWZ(mg, alk) * 16;
            ldsm4t(ah[i], addr);
            ldsm4t(al[i], addr + 4096);
        }

        #pragma unroll
        for (int jh = 0; jh < 2; jh++) {
            // 4 n-groups per half; x4 loads two n-groups (hi and lo separately)
            uint32_t bh[2][4], bl[2][4];
            #pragma unroll
            for (int jp = 0; jp < 2; jp++) {
                int ng = (n0w >> 3) + jh * 4 + jp * 2 + bngo;
                uint32_t addr = st + 8192 + bkrow * 256 + SWZ(ng, bkrow) * 16;
                ldsm4t(bh[jp], addr);
                ldsm4t(bl[jp], addr + 4096);
            }
            #pragma unroll
            for (int i = 0; i < 2; i++)
                #pragma unroll
                for (int jp = 0; jp < 2; jp++)
                    #pragma unroll
                    for (int jq = 0; jq < 2; jq++) {
                        int j = jh * 4 + jp * 2 + jq;
                        mma16816(acc[i][j], ah[i], bh[jp] + jq * 2);
                        mma16816(acc[i][j], ah[i], bl[jp] + jq * 2);
                        mma16816(acc[i][j], al[i], bh[jp] + jq * 2);
                    }
        }
    }

    // --- epilogue: scale, store l0, fused pool_l1 ---
    #pragma unroll
    for (int i = 0; i < 2; i++)
        #pragma unroll
        for (int j = 0; j < 8; j++)
            #pragma unroll
            for (int q = 0; q < 4; q++) acc[i][j][q] *= 0.0625f;

    const int qr = lane >> 2;     // 0..7
    const int qc = lane & 3;      // 0..3

    #pragma unroll
    for (int i = 0; i < 2; i++) {
        int m = mt * 128 + m0w + i * 16 + qr;
        size_t row0 = ((size_t)(b * P_ + m)) * P_;
        size_t row1 = ((size_t)(b * P_ + m + 8)) * P_;
        #pragma unroll
        for (int j = 0; j < 8; j++) {
            int nn = nt * 128 + n0w + j * 8 + qc * 2;
            *(float2*)(g_l0 + row0 + nn) = make_float2(acc[i][j][0], acc[i][j][1]);
            *(float2*)(g_l0 + row1 + nn) = make_float2(acc[i][j][2], acc[i][j][3]);
        }
    }

    // pool_l1: n-tile = image rows y=2nt (warp_n=0) + y=2nt+1 (warp_n=1)
    __syncthreads();                 // stages dead; alias as l1 buffer
    float* l1buf = (float*)smem;     // [128][33]
    if (warp_n == 0) {
        #pragma unroll
        for (int i = 0; i < 2; i++) {
            int mr = m0w + i * 16 + qr;
            #pragma unroll
            for (int j = 0; j < 8; j++) {
                int xp = j * 4 + qc;
                l1buf[mr * 33 + xp]       = acc[i][j][0] + acc[i][j][1];
                l1buf[(mr + 8) * 33 + xp] = acc[i][j][2] + acc[i][j][3];
            }
        }
    }
    __syncthreads();
    if (warp_n == 1) {
        #pragma unroll
        for (int i = 0; i < 2; i++) {
            int mr = m0w + i * 16 + qr;
            #pragma unroll
            for (int j = 0; j < 8; j++) {
                int xp = j * 4 + qc;
                l1buf[mr * 33 + xp]       += acc[i][j][0] + acc[i][j][1];
                l1buf[(mr + 8) * 33 + xp] += acc[i][j][2] + acc[i][j][3];
            }
        }
    }
    __syncthreads();
    {
        int m = tid >> 1, half = tid & 1;
        const float* sp = l1buf + m * 33 + half * 16;
        float* dst = g_l1 + ((size_t)(b * P_ + mt * 128 + m)) * 1024 + nt * 32 + half * 16;
        #pragma unroll
        for (int q = 0; q < 16; q++) dst[q] = sp[q] * 0.25f;
    }
}

// ---------------------------------------------------------------------------
// Kernel 2: fused pooling l1 -> l2 -> l3. One block per (b,p).
// ---------------------------------------------------------------------------
__global__ __launch_bounds__(256) void pool23_kernel()
{
    __shared__ float s1[1024];   // 32x32
    __shared__ float s2[256];    // 16x16
    const int bp = blockIdx.x;
    const int t = threadIdx.x;

    *(float4*)(s1 + t * 4) = *(const float4*)(g_l1 + (size_t)bp * 1024 + t * 4);
    __syncthreads();

    {
        int y = t >> 4, x = t & 15;
        const float* s = s1 + (2*y) * 32 + 2*x;
        float v = 0.25f * (s[0] + s[1] + s[32] + s[33]);
        s2[t] = v;
        g_l2[(size_t)bp * 256 + t] = v;
    }
    __syncthreads();

    if (t < 64) {
        int y = t >> 3, x = t & 7;
        const float* s = s2 + (2*y) * 16 + 2*x;
        g_l3[(size_t)bp * 64 + t] = 0.25f * (s[0] + s[1] + s[16] + s[17]);
    }
}

// ---------------------------------------------------------------------------
// Kernel 3: window gather + bilinear
// ---------------------------------------------------------------------------
__global__ __launch_bounds__(256) void gather_kernel(
    const float* __restrict__ coords, float* __restrict__ out)
{
    __shared__ float patch[8][104];

    const int wl   = threadIdx.x >> 5;
    const int lane = threadIdx.x & 31;
    unsigned w = blockIdx.x * 8u + wl;

    const int l = w & 3;  w >>= 2;
    const int p = w & (P_ - 1); w >>= 12;
    const int n = w & 3;
    const int b = w >> 2;

    const float cx = coords[((size_t)((b * N_ + n) * 2 + 0)) * P_ + p];
    const float cy = coords[((size_t)((b * N_ + n) * 2 + 1)) * P_ + p];

    const float inv = 1.0f / (float)(1 << l);
    const float xs = cx * inv;
    const float ys = cy * inv;
    const float x0f = floorf(xs);
    const float y0f = floorf(ys);
    const float fx = xs - x0f;
    const float fy = ys - y0f;
    const int x0 = (int)x0f;
    const int y0 = (int)y0f;
    const int sz = 64 >> l;

    const float* base;
    switch (l) {
        case 0:  base = g_l0; break;
        case 1:  base = g_l1; break;
        case 2:  base = g_l2; break;
        default: base = g_l3; break;
    }
    base += (size_t)(b * P_ + p) * sz * sz;

    #pragma unroll
    for (int t = lane; t < 100; t += 32) {
        int j = t / 10, i = t % 10;
        int yy = y0 - 4 + j;
        int xx = x0 - 4 + i;
        float v = 0.0f;
        if ((unsigned)yy < (unsigned)sz && (unsigned)xx < (unsigned)sz)
            v = base[yy * sz + xx];
        patch[wl][t] = v;
    }
    __syncwarp();

    const float w00 = (1.0f - fy) * (1.0f - fx);
    const float w01 = (1.0f - fy) * fx;
    const float w10 = fy * (1.0f - fx);
    const float w11 = fy * fx;

    float* ob = out + ((size_t)((b * N_ + n) * P_ + p)) * CTOT_ + l * K2_;

    #pragma unroll
    for (int k = lane; k < K2_; k += 32) {
        int ix = k / 9;
        int iy = k % 9;
        float v00 = patch[wl][iy * 10 + ix];
        float v01 = patch[wl][iy * 10 + ix + 1];
        float v10 = patch[wl][(iy + 1) * 10 + ix];
        float v11 = patch[wl][(iy + 1) * 10 + ix + 1];
        ob[k] = w00 * v00 + w01 * v01 + w10 * v10 + w11 * v11;
    }
}

// ---------------------------------------------------------------------------
extern "C" void kernel_launch(void* const* d_in, const int* in_sizes, int n_in,
                              void* d_out, int out_size)
{
    const float* f1     = (const float*)d_in[0];
    const float* f2     = (const float*)d_in[1];
    const float* coords = (const float*)d_in[2];
    float* out = (float*)d_out;

    // 0) bf16 split, both tensors in one launch
    dim3 cgrid((B_ * C_ * P_) / (256 * 4), 2);   // (2048, 2)
    convert_kernel<<<cgrid, 256>>>(f1, f2);

    // 1) HMMA correlation GEMM (+ fused pool_l1)
    dim3 gg(32, 32, 2);
    gemm_hmma_kernel<<<gg, 256>>>();

    // 2) fused pyramid tail (l2 + l3)
    pool23_kernel<<<B_ * P_, 256>>>();

    // 3) gather
    gather_kernel<<<(B_ * N_ * P_ * 4) / 8, 256>>>(coords, out);
}

// round 7
// speedup vs baseline: 3.2269x; 1.4611x over previous
#include <cuda_runtime.h>
#include <cuda_fp16.h>
#include <cstdint>

// Problem constants
#define B_ 2
#define C_ 256
#define H_ 64
#define W_ 64
#define P_ 4096
#define N_ 4
#define K2_ 81
#define CTOT_ 324

// ---------------------------------------------------------------------------
// Device scratch (allocation-free per harness rules)
// ---------------------------------------------------------------------------
__device__ float g_l0[(size_t)B_*P_*64*64];  // 128 MiB
__device__ float g_l1[(size_t)B_*P_*32*32];  //  32 MiB
__device__ float g_l2[(size_t)B_*P_*16*16];  //   8 MiB
__device__ float g_l3[(size_t)B_*P_*8*8];    //   2 MiB

// fp16 operands, layout [b][c][p] (same as inputs)
__device__ __half gA[(size_t)B_*C_*P_];
__device__ __half gB[(size_t)B_*C_*P_];

// ---------------------------------------------------------------------------
// PTX helpers (base sm_80-class features only)
// ---------------------------------------------------------------------------
__device__ __forceinline__ uint32_t smem_u32(const void* p) {
    uint32_t a;
    asm("{ .reg .u64 t; cvta.to.shared.u64 t, %1; cvt.u32.u64 %0, t; }" : "=r"(a) : "l"(p));
    return a;
}
__device__ __forceinline__ void cp16(uint32_t d, const void* s) {
    asm volatile("cp.async.cg.shared.global [%0], [%1], 16;" :: "r"(d), "l"(s));
}
__device__ __forceinline__ void cp_commit() {
    asm volatile("cp.async.commit_group;" ::: "memory");
}
__device__ __forceinline__ void ldsm4t(uint32_t* r, uint32_t a) {
    asm volatile("ldmatrix.sync.aligned.m8n8.x4.trans.shared.b16 {%0,%1,%2,%3}, [%4];"
        : "=r"(r[0]), "=r"(r[1]), "=r"(r[2]), "=r"(r[3]) : "r"(a));
}
__device__ __forceinline__ void mma16816(float* c, const uint32_t* a, const uint32_t* b) {
    asm volatile("mma.sync.aligned.m16n8k16.row.col.f32.f16.f16.f32 "
        "{%0,%1,%2,%3}, {%4,%5,%6,%7}, {%8,%9}, {%0,%1,%2,%3};"
        : "+f"(c[0]), "+f"(c[1]), "+f"(c[2]), "+f"(c[3])
        : "r"(a[0]), "r"(a[1]), "r"(a[2]), "r"(a[3]), "r"(b[0]), "r"(b[1]));
}

// XOR swizzle of 16B group index g within a 256B k-row (bank period 128B = 8 groups)
#define SWZ(g, k) (((g) & 8) | (((g) ^ (k)) & 7))

// ---------------------------------------------------------------------------
// Kernel 0: fp32 -> fp16, both tensors in one launch. Device globals
// referenced in device code only (host shadow symbols alias host mem via ATS).
// ---------------------------------------------------------------------------
__global__ __launch_bounds__(256) void convert_kernel(
    const float* __restrict__ f1, const float* __restrict__ f2)
{
    const int which = blockIdx.y;
    const float* __restrict__ src = which ? f2 : f1;
    __half* __restrict__ dst = which ? gB : gA;

    size_t i = ((size_t)blockIdx.x * 256 + threadIdx.x) * 4;
    float4 v = *(const float4*)(src + i);
    __half2 h0 = __floats2half2_rn(v.x, v.y);
    __half2 h1 = __floats2half2_rn(v.z, v.w);
    *(uint2*)((unsigned char*)dst + i * 2) =
        make_uint2(*(uint32_t*)&h0, *(uint32_t*)&h1);
}

// ---------------------------------------------------------------------------
// Kernel 1: HMMA fp16 correlation GEMM + fused pool_l1.
// Block tile 128x128, K=256 in 16 chunks of 16, SINGLE fp16 term.
// 8 warps = 4(m) x 2(n); warp tile 32x64. 3-stage cp.async pipeline.
// Stage (8KB): Ah | Bh, each 16 k-rows x 256B, swizzled.
// ---------------------------------------------------------------------------
__global__ __launch_bounds__(256, 2) void gemm_hmma_kernel()
{
    __shared__ __align__(1024) unsigned char smem[24576];   // 3 x 8KB stages
    const uint32_t sbase = smem_u32(smem);

    const int tid  = threadIdx.x;
    const int lane = tid & 31;
    const int wid  = tid >> 5;
    const int nt = blockIdx.x, mt = blockIdx.y, b = blockIdx.z;
    const int warp_m = wid & 3, warp_n = wid >> 2;
    const int m0w = warp_m * 32, n0w = warp_n * 64;

    // --- cp.async mapping: thread -> (k row, 16B group) ---
    const int ck = tid >> 4;        // 0..15
    const int cg = tid & 15;        // 0..15
    const uint32_t cdst = ck * 256 + SWZ(cg, ck) * 16;
    const size_t gsrc_a = ((size_t)b * C_ + ck) * P_ + mt * 128 + cg * 8;
    const size_t gsrc_b = ((size_t)b * C_ + ck) * P_ + nt * 128 + cg * 8;

    auto prefetch = [&](int s, int c) {
        uint32_t st = sbase + s * 8192 + cdst;
        size_t koff = (size_t)c * 16 * P_;
        cp16(st +    0, gA + gsrc_a + koff);
        cp16(st + 4096, gB + gsrc_b + koff);
        cp_commit();
    };

    // --- ldmatrix lane addressing (validated in rounds 4-6) ---
    const int alk   = (lane & 7) | ((lane & 16) >> 1); // A: k row 0..15
    const int amsel = (lane >> 3) & 1;                 // A: m-group select
    const int bkrow = (lane & 7) | ((lane & 8));       // B: k row 0..15
    const int bngo  = (lane >> 4) & 1;                 // B: +0 / +1 n-group

    float acc[2][8][4];
    #pragma unroll
    for (int i = 0; i < 2; i++)
        #pragma unroll
        for (int j = 0; j < 8; j++)
            #pragma unroll
            for (int q = 0; q < 4; q++) acc[i][j][q] = 0.0f;

    prefetch(0, 0);
    prefetch(1, 1);

    for (int c = 0; c < 16; c++) {
        if (c < 14) asm volatile("cp.async.wait_group 1;" ::: "memory");
        else        asm volatile("cp.async.wait_group 0;" ::: "memory");
        __syncthreads();
        if (c + 2 < 16) prefetch((c + 2) % 3, c + 2);

        uint32_t st = sbase + (c % 3) * 8192;

        uint32_t ah[2][4];
        #pragma unroll
        for (int i = 0; i < 2; i++) {
            int mg = (m0w >> 3) + i * 2 + amsel;
            ldsm4t(ah[i], st + alk * 256 + SWZ(mg, alk) * 16);
        }

        uint32_t bh[4][4];
        #pragma unroll
        for (int jp = 0; jp < 4; jp++) {
            int ng = (n0w >> 3) + jp * 2 + bngo;
            ldsm4t(bh[jp], st + 4096 + bkrow * 256 + SWZ(ng, bkrow) * 16);
        }

        #pragma unroll
        for (int i = 0; i < 2; i++)
            #pragma unroll
            for (int jp = 0; jp < 4; jp++)
                #pragma unroll
                for (int jq = 0; jq < 2; jq++)
                    mma16816(acc[i][jp * 2 + jq], ah[i], bh[jp] + jq * 2);
    }

    // --- epilogue: scale, store l0, fused pool_l1 ---
    #pragma unroll
    for (int i = 0; i < 2; i++)
        #pragma unroll
        for (int j = 0; j < 8; j++)
            #pragma unroll
            for (int q = 0; q < 4; q++) acc[i][j][q] *= 0.0625f;

    const int qr = lane >> 2;     // 0..7
    const int qc = lane & 3;      // 0..3

    #pragma unroll
    for (int i = 0; i < 2; i++) {
        int m = mt * 128 + m0w + i * 16 + qr;
        size_t row0 = ((size_t)(b * P_ + m)) * P_;
        size_t row1 = ((size_t)(b * P_ + m + 8)) * P_;
        #pragma unroll
        for (int j = 0; j < 8; j++) {
            int nn = nt * 128 + n0w + j * 8 + qc * 2;
            *(float2*)(g_l0 + row0 + nn) = make_float2(acc[i][j][0], acc[i][j][1]);
            *(float2*)(g_l0 + row1 + nn) = make_float2(acc[i][j][2], acc[i][j][3]);
        }
    }

    // pool_l1: n-tile = image rows y=2nt (warp_n=0) + y=2nt+1 (warp_n=1)
    __syncthreads();                 // stages dead; alias as l1 buffer
    float* l1buf = (float*)smem;     // [128][33] = 16.9KB < 24KB
    if (warp_n == 0) {
        #pragma unroll
        for (int i = 0; i < 2; i++) {
            int mr = m0w + i * 16 + qr;
            #pragma unroll
            for (int j = 0; j < 8; j++) {
                int xp = j * 4 + qc;
                l1buf[mr * 33 + xp]       = acc[i][j][0] + acc[i][j][1];
                l1buf[(mr + 8) * 33 + xp] = acc[i][j][2] + acc[i][j][3];
            }
        }
    }
    __syncthreads();
    if (warp_n == 1) {
        #pragma unroll
        for (int i = 0; i < 2; i++) {
            int mr = m0w + i * 16 + qr;
            #pragma unroll
            for (int j = 0; j < 8; j++) {
                int xp = j * 4 + qc;
                l1buf[mr * 33 + xp]       += acc[i][j][0] + acc[i][j][1];
                l1buf[(mr + 8) * 33 + xp] += acc[i][j][2] + acc[i][j][3];
            }
        }
    }
    __syncthreads();
    {
        int m = tid >> 1, half = tid & 1;
        const float* sp = l1buf + m * 33 + half * 16;
        float* dst = g_l1 + ((size_t)(b * P_ + mt * 128 + m)) * 1024 + nt * 32 + half * 16;
        #pragma unroll
        for (int q = 0; q < 16; q++) dst[q] = sp[q] * 0.25f;
    }
}

// ---------------------------------------------------------------------------
// Kernel 2: fused pooling l1 -> l2 -> l3. One block per (b,p).
// ---------------------------------------------------------------------------
__global__ __launch_bounds__(256) void pool23_kernel()
{
    __shared__ float s1[1024];   // 32x32
    __shared__ float s2[256];    // 16x16
    const int bp = blockIdx.x;
    const int t = threadIdx.x;

    *(float4*)(s1 + t * 4) = *(const float4*)(g_l1 + (size_t)bp * 1024 + t * 4);
    __syncthreads();

    {
        int y = t >> 4, x = t & 15;
        const float* s = s1 + (2*y) * 32 + 2*x;
        float v = 0.25f * (s[0] + s[1] + s[32] + s[33]);
        s2[t] = v;
        g_l2[(size_t)bp * 256 + t] = v;
    }
    __syncthreads();

    if (t < 64) {
        int y = t >> 3, x = t & 7;
        const float* s = s2 + (2*y) * 16 + 2*x;
        g_l3[(size_t)bp * 64 + t] = 0.25f * (s[0] + s[1] + s[16] + s[17]);
    }
}

// ---------------------------------------------------------------------------
// Kernel 3: window gather + bilinear
// ---------------------------------------------------------------------------
__global__ __launch_bounds__(256) void gather_kernel(
    const float* __restrict__ coords, float* __restrict__ out)
{
    __shared__ float patch[8][104];

    const int wl   = threadIdx.x >> 5;
    const int lane = threadIdx.x & 31;
    unsigned w = blockIdx.x * 8u + wl;

    const int l = w & 3;  w >>= 2;
    const int p = w & (P_ - 1); w >>= 12;
    const int n = w & 3;
    const int b = w >> 2;

    const float cx = coords[((size_t)((b * N_ + n) * 2 + 0)) * P_ + p];
    const float cy = coords[((size_t)((b * N_ + n) * 2 + 1)) * P_ + p];

    const float inv = 1.0f / (float)(1 << l);
    const float xs = cx * inv;
    const float ys = cy * inv;
    const float x0f = floorf(xs);
    const float y0f = floorf(ys);
    const float fx = xs - x0f;
    const float fy = ys - y0f;
    const int x0 = (int)x0f;
    const int y0 = (int)y0f;
    const int sz = 64 >> l;

    const float* base;
    switch (l) {
        case 0:  base = g_l0; break;
        case 1:  base = g_l1; break;
        case 2:  base = g_l2; break;
        default: base = g_l3; break;
    }
    base += (size_t)(b * P_ + p) * sz * sz;

    #pragma unroll
    for (int t = lane; t < 100; t += 32) {
        int j = t / 10, i = t % 10;
        int yy = y0 - 4 + j;
        int xx = x0 - 4 + i;
        float v = 0.0f;
        if ((unsigned)yy < (unsigned)sz && (unsigned)xx < (unsigned)sz)
            v = base[yy * sz + xx];
        patch[wl][t] = v;
    }
    __syncwarp();

    const float w00 = (1.0f - fy) * (1.0f - fx);
    const float w01 = (1.0f - fy) * fx;
    const float w10 = fy * (1.0f - fx);
    const float w11 = fy * fx;

    float* ob = out + ((size_t)((b * N_ + n) * P_ + p)) * CTOT_ + l * K2_;

    #pragma unroll
    for (int k = lane; k < K2_; k += 32) {
        int ix = k / 9;
        int iy = k % 9;
        float v00 = patch[wl][iy * 10 + ix];
        float v01 = patch[wl][iy * 10 + ix + 1];
        float v10 = patch[wl][(iy + 1) * 10 + ix];
        float v11 = patch[wl][(iy + 1) * 10 + ix + 1];
        ob[k] = w00 * v00 + w01 * v01 + w10 * v10 + w11 * v11;
    }
}

// ---------------------------------------------------------------------------
extern "C" void kernel_launch(void* const* d_in, const int* in_sizes, int n_in,
                              void* d_out, int out_size)
{
    const float* f1     = (const float*)d_in[0];
    const float* f2     = (const float*)d_in[1];
    const float* coords = (const float*)d_in[2];
    float* out = (float*)d_out;

    // 0) fp32 -> fp16, both tensors in one launch
    dim3 cgrid((B_ * C_ * P_) / (256 * 4), 2);   // (2048, 2)
    convert_kernel<<<cgrid, 256>>>(f1, f2);

    // 1) HMMA fp16 correlation GEMM (+ fused pool_l1)
    dim3 gg(32, 32, 2);
    gemm_hmma_kernel<<<gg, 256>>>();

    // 2) fused pyramid tail (l2 + l3)
    pool23_kernel<<<B_ * P_, 256>>>();

    // 3) gather
    gather_kernel<<<(B_ * N_ * P_ * 4) / 8, 256>>>(coords, out);
}

// round 8
// speedup vs baseline: 3.4078x; 1.0561x over previous
#include <cuda_runtime.h>
#include <cuda_fp16.h>
#include <cstdint>

// Problem constants
#define B_ 2
#define C_ 256
#define H_ 64
#define W_ 64
#define P_ 4096
#define N_ 4
#define K2_ 81
#define CTOT_ 324

// ---------------------------------------------------------------------------
// Device scratch (allocation-free per harness rules)
// ---------------------------------------------------------------------------
__device__ float g_l0[(size_t)B_*P_*64*64];  // 128 MiB
__device__ float g_l1[(size_t)B_*P_*32*32];  //  32 MiB
__device__ float g_l2[(size_t)B_*P_*16*16];  //   8 MiB
__device__ float g_l3[(size_t)B_*P_*8*8];    //   2 MiB

// fp16 operands, layout [b][c][p] (same as inputs)
__device__ __half gA[(size_t)B_*C_*P_];
__device__ __half gB[(size_t)B_*C_*P_];

// ---------------------------------------------------------------------------
// PTX helpers (base sm_80-class features only)
// ---------------------------------------------------------------------------
__device__ __forceinline__ uint32_t smem_u32(const void* p) {
    uint32_t a;
    asm("{ .reg .u64 t; cvta.to.shared.u64 t, %1; cvt.u32.u64 %0, t; }" : "=r"(a) : "l"(p));
    return a;
}
__device__ __forceinline__ void cp16(uint32_t d, const void* s) {
    asm volatile("cp.async.cg.shared.global [%0], [%1], 16;" :: "r"(d), "l"(s));
}
__device__ __forceinline__ void cp_commit() {
    asm volatile("cp.async.commit_group;" ::: "memory");
}
__device__ __forceinline__ void ldsm4t(uint32_t* r, uint32_t a) {
    asm volatile("ldmatrix.sync.aligned.m8n8.x4.trans.shared.b16 {%0,%1,%2,%3}, [%4];"
        : "=r"(r[0]), "=r"(r[1]), "=r"(r[2]), "=r"(r[3]) : "r"(a));
}
__device__ __forceinline__ void mma16816(float* c, const uint32_t* a, const uint32_t* b) {
    asm volatile("mma.sync.aligned.m16n8k16.row.col.f32.f16.f16.f32 "
        "{%0,%1,%2,%3}, {%4,%5,%6,%7}, {%8,%9}, {%0,%1,%2,%3};"
        : "+f"(c[0]), "+f"(c[1]), "+f"(c[2]), "+f"(c[3])
        : "r"(a[0]), "r"(a[1]), "r"(a[2]), "r"(a[3]), "r"(b[0]), "r"(b[1]));
}

// XOR swizzle of 16B group index g within a 256B k-row
#define SWZ(g, k) (((g) & 8) | (((g) ^ (k)) & 7))

// ---------------------------------------------------------------------------
// Kernel 0: fp32 -> fp16, both tensors in one launch.
// ---------------------------------------------------------------------------
__global__ __launch_bounds__(256) void convert_kernel(
    const float* __restrict__ f1, const float* __restrict__ f2)
{
    const int which = blockIdx.y;
    const float* __restrict__ src = which ? f2 : f1;
    __half* __restrict__ dst = which ? gB : gA;

    size_t i = ((size_t)blockIdx.x * 256 + threadIdx.x) * 4;
    float4 v = *(const float4*)(src + i);
    __half2 h0 = __floats2half2_rn(v.x, v.y);
    __half2 h1 = __floats2half2_rn(v.z, v.w);
    *(uint2*)((unsigned char*)dst + i * 2) =
        make_uint2(*(uint32_t*)&h0, *(uint32_t*)&h1);
}

// ---------------------------------------------------------------------------
// Kernel 1: HMMA fp16 correlation GEMM + fused pool_l1 (validated r7).
// ---------------------------------------------------------------------------
__global__ __launch_bounds__(256, 2) void gemm_hmma_kernel()
{
    __shared__ __align__(1024) unsigned char smem[24576];   // 3 x 8KB stages
    const uint32_t sbase = smem_u32(smem);

    const int tid  = threadIdx.x;
    const int lane = tid & 31;
    const int wid  = tid >> 5;
    const int nt = blockIdx.x, mt = blockIdx.y, b = blockIdx.z;
    const int warp_m = wid & 3, warp_n = wid >> 2;
    const int m0w = warp_m * 32, n0w = warp_n * 64;

    const int ck = tid >> 4;
    const int cg = tid & 15;
    const uint32_t cdst = ck * 256 + SWZ(cg, ck) * 16;
    const size_t gsrc_a = ((size_t)b * C_ + ck) * P_ + mt * 128 + cg * 8;
    const size_t gsrc_b = ((size_t)b * C_ + ck) * P_ + nt * 128 + cg * 8;

    auto prefetch = [&](int s, int c) {
        uint32_t st = sbase + s * 8192 + cdst;
        size_t koff = (size_t)c * 16 * P_;
        cp16(st +    0, gA + gsrc_a + koff);
        cp16(st + 4096, gB + gsrc_b + koff);
        cp_commit();
    };

    const int alk   = (lane & 7) | ((lane & 16) >> 1);
    const int amsel = (lane >> 3) & 1;
    const int bkrow = (lane & 7) | ((lane & 8));
    const int bngo  = (lane >> 4) & 1;

    float acc[2][8][4];
    #pragma unroll
    for (int i = 0; i < 2; i++)
        #pragma unroll
        for (int j = 0; j < 8; j++)
            #pragma unroll
            for (int q = 0; q < 4; q++) acc[i][j][q] = 0.0f;

    prefetch(0, 0);
    prefetch(1, 1);

    for (int c = 0; c < 16; c++) {
        if (c < 14) asm volatile("cp.async.wait_group 1;" ::: "memory");
        else        asm volatile("cp.async.wait_group 0;" ::: "memory");
        __syncthreads();
        if (c + 2 < 16) prefetch((c + 2) % 3, c + 2);

        uint32_t st = sbase + (c % 3) * 8192;

        uint32_t ah[2][4];
        #pragma unroll
        for (int i = 0; i < 2; i++) {
            int mg = (m0w >> 3) + i * 2 + amsel;
            ldsm4t(ah[i], st + alk * 256 + SWZ(mg, alk) * 16);
        }

        uint32_t bh[4][4];
        #pragma unroll
        for (int jp = 0; jp < 4; jp++) {
            int ng = (n0w >> 3) + jp * 2 + bngo;
            ldsm4t(bh[jp], st + 4096 + bkrow * 256 + SWZ(ng, bkrow) * 16);
        }

        #pragma unroll
        for (int i = 0; i < 2; i++)
            #pragma unroll
            for (int jp = 0; jp < 4; jp++)
                #pragma unroll
                for (int jq = 0; jq < 2; jq++)
                    mma16816(acc[i][jp * 2 + jq], ah[i], bh[jp] + jq * 2);
    }

    #pragma unroll
    for (int i = 0; i < 2; i++)
        #pragma unroll
        for (int j = 0; j < 8; j++)
            #pragma unroll
            for (int q = 0; q < 4; q++) acc[i][j][q] *= 0.0625f;

    const int qr = lane >> 2;
    const int qc = lane & 3;

    #pragma unroll
    for (int i = 0; i < 2; i++) {
        int m = mt * 128 + m0w + i * 16 + qr;
        size_t row0 = ((size_t)(b * P_ + m)) * P_;
        size_t row1 = ((size_t)(b * P_ + m + 8)) * P_;
        #pragma unroll
        for (int j = 0; j < 8; j++) {
            int nn = nt * 128 + n0w + j * 8 + qc * 2;
            *(float2*)(g_l0 + row0 + nn) = make_float2(acc[i][j][0], acc[i][j][1]);
            *(float2*)(g_l0 + row1 + nn) = make_float2(acc[i][j][2], acc[i][j][3]);
        }
    }

    __syncthreads();
    float* l1buf = (float*)smem;     // [128][33]
    if (warp_n == 0) {
        #pragma unroll
        for (int i = 0; i < 2; i++) {
            int mr = m0w + i * 16 + qr;
            #pragma unroll
            for (int j = 0; j < 8; j++) {
                int xp = j * 4 + qc;
                l1buf[mr * 33 + xp]       = acc[i][j][0] + acc[i][j][1];
                l1buf[(mr + 8) * 33 + xp] = acc[i][j][2] + acc[i][j][3];
            }
        }
    }
    __syncthreads();
    if (warp_n == 1) {
        #pragma unroll
        for (int i = 0; i < 2; i++) {
            int mr = m0w + i * 16 + qr;
            #pragma unroll
            for (int j = 0; j < 8; j++) {
                int xp = j * 4 + qc;
                l1buf[mr * 33 + xp]       += acc[i][j][0] + acc[i][j][1];
                l1buf[(mr + 8) * 33 + xp] += acc[i][j][2] + acc[i][j][3];
            }
        }
    }
    __syncthreads();
    {
        int m = tid >> 1, half = tid & 1;
        const float* sp = l1buf + m * 33 + half * 16;
        float* dst = g_l1 + ((size_t)(b * P_ + mt * 128 + m)) * 1024 + nt * 32 + half * 16;
        #pragma unroll
        for (int q = 0; q < 16; q++) dst[q] = sp[q] * 0.25f;
    }
}

// ---------------------------------------------------------------------------
// Kernel 2: fused pooling l1 -> l2 -> l3. One block per (b,p).
// ---------------------------------------------------------------------------
__global__ __launch_bounds__(256) void pool23_kernel()
{
    __shared__ float s1[1024];
    __shared__ float s2[256];
    const int bp = blockIdx.x;
    const int t = threadIdx.x;

    *(float4*)(s1 + t * 4) = *(const float4*)(g_l1 + (size_t)bp * 1024 + t * 4);
    __syncthreads();

    {
        int y = t >> 4, x = t & 15;
        const float* s = s1 + (2*y) * 32 + 2*x;
        float v = 0.25f * (s[0] + s[1] + s[32] + s[33]);
        s2[t] = v;
        g_l2[(size_t)bp * 256 + t] = v;
    }
    __syncthreads();

    if (t < 64) {
        int y = t >> 3, x = t & 7;
        const float* s = s2 + (2*y) * 16 + 2*x;
        g_l3[(size_t)bp * 64 + t] = 0.25f * (s[0] + s[1] + s[16] + s[17]);
    }
}

// ---------------------------------------------------------------------------
// Kernel 3: window gather + bilinear, ALL 4 LEVELS per warp.
// One warp per (b,n,p): coords + k/9,k%9 computed once; 324-float output
// assembled in smem, stored as 81 coalesced float4 (1296B per query, 16B
// aligned since 1296 = 81*16).
// ---------------------------------------------------------------------------
__global__ __launch_bounds__(256) void gather_kernel(
    const float* __restrict__ coords, float* __restrict__ out)
{
    __shared__ float patch_s[8][104];
    __shared__ __align__(16) float out_s[8][CTOT_];

    const int wl   = threadIdx.x >> 5;
    const int lane = threadIdx.x & 31;
    unsigned w = blockIdx.x * 8u + wl;   // 0 .. 32767 = (b,n,p)

    const int p = w & (P_ - 1); w >>= 12;
    const int n = w & 3;
    const int b = w >> 2;

    const float cx = coords[((size_t)((b * N_ + n) * 2 + 0)) * P_ + p];
    const float cy = coords[((size_t)((b * N_ + n) * 2 + 1)) * P_ + p];

    // per-lane output indices (constant across levels)
    const int k1 = lane + 32, k2 = lane + 64;       // k0 = lane
    const int ix0 = lane / 9, iy0 = lane % 9;
    const int ix1 = k1 / 9,   iy1 = k1 % 9;
    const int ix2 = k2 / 9,   iy2 = k2 % 9;         // valid if k2 < 81

    // per-lane patch-load indices (constant across levels)
    const int pj0 = lane / 10,      pi0 = lane % 10;
    const int pj1 = (lane+32) / 10, pi1 = (lane+32) % 10;
    const int pj2 = (lane+64) / 10, pi2 = (lane+64) % 10;
    const int pj3 = (lane+96) / 10, pi3 = (lane+96) % 10;   // lanes 0..3

    float* pw = patch_s[wl];
    float* ow = out_s[wl];

    #pragma unroll
    for (int l = 0; l < 4; l++) {
        const int sz = 64 >> l;
        const float inv = 1.0f / (float)(1 << l);
        const float* base;
        switch (l) {
            case 0:  base = g_l0; break;
            case 1:  base = g_l1; break;
            case 2:  base = g_l2; break;
            default: base = g_l3; break;
        }
        base += (size_t)(b * P_ + p) * sz * sz;

        const float xs = cx * inv;
        const float ys = cy * inv;
        const float x0f = floorf(xs);
        const float y0f = floorf(ys);
        const float fx = xs - x0f;
        const float fy = ys - y0f;
        const int x0 = (int)x0f;
        const int y0 = (int)y0f;

        // load 10x10 zero-padded patch
        {
            int yy, xx; float v;
            yy = y0 - 4 + pj0; xx = x0 - 4 + pi0; v = 0.0f;
            if ((unsigned)yy < (unsigned)sz && (unsigned)xx < (unsigned)sz) v = base[yy*sz + xx];
            pw[lane] = v;
            yy = y0 - 4 + pj1; xx = x0 - 4 + pi1; v = 0.0f;
            if ((unsigned)yy < (unsigned)sz && (unsigned)xx < (unsigned)sz) v = base[yy*sz + xx];
            pw[lane + 32] = v;
            yy = y0 - 4 + pj2; xx = x0 - 4 + pi2; v = 0.0f;
            if ((unsigned)yy < (unsigned)sz && (unsigned)xx < (unsigned)sz) v = base[yy*sz + xx];
            pw[lane + 64] = v;
            if (lane < 4) {
                yy = y0 - 4 + pj3; xx = x0 - 4 + pi3; v = 0.0f;
                if ((unsigned)yy < (unsigned)sz && (unsigned)xx < (unsigned)sz) v = base[yy*sz + xx];
                pw[lane + 96] = v;
            }
        }
        __syncwarp();

        const float w00 = (1.0f - fy) * (1.0f - fx);
        const float w01 = (1.0f - fy) * fx;
        const float w10 = fy * (1.0f - fx);
        const float w11 = fy * fx;
        float* ob = ow + l * K2_;

        {
            float v00 = pw[iy0*10 + ix0],     v01 = pw[iy0*10 + ix0 + 1];
            float v10 = pw[(iy0+1)*10 + ix0], v11 = pw[(iy0+1)*10 + ix0 + 1];
            ob[lane] = w00*v00 + w01*v01 + w10*v10 + w11*v11;
        }
        {
            float v00 = pw[iy1*10 + ix1],     v01 = pw[iy1*10 + ix1 + 1];
            float v10 = pw[(iy1+1)*10 + ix1], v11 = pw[(iy1+1)*10 + ix1 + 1];
            ob[k1] = w00*v00 + w01*v01 + w10*v10 + w11*v11;
        }
        if (k2 < K2_) {
            float v00 = pw[iy2*10 + ix2],     v01 = pw[iy2*10 + ix2 + 1];
            float v10 = pw[(iy2+1)*10 + ix2], v11 = pw[(iy2+1)*10 + ix2 + 1];
            ob[k2] = w00*v00 + w01*v01 + w10*v10 + w11*v11;
        }
        __syncwarp();   // before next level overwrites the patch
    }

    // coalesced float4 stores: 81 per warp
    const float4* os = (const float4*)ow;
    float4* dst = (float4*)(out + ((size_t)((b * N_ + n) * P_ + p)) * CTOT_);
    dst[lane]      = os[lane];
    dst[lane + 32] = os[lane + 32];
    if (lane < 17) dst[lane + 64] = os[lane + 64];
}

// ---------------------------------------------------------------------------
extern "C" void kernel_launch(void* const* d_in, const int* in_sizes, int n_in,
                              void* d_out, int out_size)
{
    const float* f1     = (const float*)d_in[0];
    const float* f2     = (const float*)d_in[1];
    const float* coords = (const float*)d_in[2];
    float* out = (float*)d_out;

    // 0) fp32 -> fp16
    dim3 cgrid((B_ * C_ * P_) / (256 * 4), 2);
    convert_kernel<<<cgrid, 256>>>(f1, f2);

    // 1) HMMA fp16 correlation GEMM (+ fused pool_l1)
    dim3 gg(32, 32, 2);
    gemm_hmma_kernel<<<gg, 256>>>();

    // 2) fused pyramid tail (l2 + l3)
    pool23_kernel<<<B_ * P_, 256>>>();

    // 3) gather: one warp per (b,n,p) = 32768 warps, 8/block
    gather_kernel<<<(B_ * N_ * P_) / 8, 256>>>(coords, out);
}

// round 10
// speedup vs baseline: 4.2799x; 1.2559x over previous
#include <cuda_runtime.h>
#include <cuda_fp16.h>
#include <cstdint>

// Problem constants
#define B_ 2
#define C_ 256
#define H_ 64
#define W_ 64
#define P_ 4096
#define N_ 4
#define K2_ 81
#define CTOT_ 324

// ---------------------------------------------------------------------------
// Device scratch (allocation-free per harness rules)
// l0/l1 in fp16 (big, bandwidth-bound); l2/l3 fp32 (tiny, avoid extra rounding)
// ---------------------------------------------------------------------------
__device__ __half g_l0[(size_t)B_*P_*64*64];  // 64 MiB
__device__ __half g_l1[(size_t)B_*P_*32*32];  // 16 MiB
__device__ float  g_l2[(size_t)B_*P_*16*16];  //  8 MiB
__device__ float  g_l3[(size_t)B_*P_*8*8];    //  2 MiB

// fp16 operands, layout [b][c][p] (same as inputs)
__device__ __half gA[(size_t)B_*C_*P_];
__device__ __half gB[(size_t)B_*C_*P_];

// ---------------------------------------------------------------------------
// PTX helpers (base sm_80-class features only)
// ---------------------------------------------------------------------------
__device__ __forceinline__ uint32_t smem_u32(const void* p) {
    uint32_t a;
    asm("{ .reg .u64 t; cvta.to.shared.u64 t, %1; cvt.u32.u64 %0, t; }" : "=r"(a) : "l"(p));
    return a;
}
__device__ __forceinline__ void cp16(uint32_t d, const void* s) {
    asm volatile("cp.async.cg.shared.global [%0], [%1], 16;" :: "r"(d), "l"(s));
}
__device__ __forceinline__ void cp_commit() {
    asm volatile("cp.async.commit_group;" ::: "memory");
}
__device__ __forceinline__ void ldsm4t(uint32_t* r, uint32_t a) {
    asm volatile("ldmatrix.sync.aligned.m8n8.x4.trans.shared.b16 {%0,%1,%2,%3}, [%4];"
        : "=r"(r[0]), "=r"(r[1]), "=r"(r[2]), "=r"(r[3]) : "r"(a));
}
__device__ __forceinline__ void mma16816(float* c, const uint32_t* a, const uint32_t* b) {
    asm volatile("mma.sync.aligned.m16n8k16.row.col.f32.f16.f16.f32 "
        "{%0,%1,%2,%3}, {%4,%5,%6,%7}, {%8,%9}, {%0,%1,%2,%3};"
        : "+f"(c[0]), "+f"(c[1]), "+f"(c[2]), "+f"(c[3])
        : "r"(a[0]), "r"(a[1]), "r"(a[2]), "r"(a[3]), "r"(b[0]), "r"(b[1]));
}

// XOR swizzle of 16B group index g within a 256B k-row
#define SWZ(g, k) (((g) & 8) | (((g) ^ (k)) & 7))

// ---------------------------------------------------------------------------
// Kernel 0: fp32 -> fp16, both tensors in one launch.
// ---------------------------------------------------------------------------
__global__ __launch_bounds__(256) void convert_kernel(
    const float* __restrict__ f1, const float* __restrict__ f2)
{
    const int which = blockIdx.y;
    const float* __restrict__ src = which ? f2 : f1;
    __half* __restrict__ dst = which ? gB : gA;

    size_t i = ((size_t)blockIdx.x * 256 + threadIdx.x) * 4;
    float4 v = *(const float4*)(src + i);
    __half2 h0 = __floats2half2_rn(v.x, v.y);
    __half2 h1 = __floats2half2_rn(v.z, v.w);
    *(uint2*)((unsigned char*)dst + i * 2) =
        make_uint2(*(uint32_t*)&h0, *(uint32_t*)&h1);
}

// ---------------------------------------------------------------------------
// Kernel 1: HMMA fp16 correlation GEMM + fused pool_l1.
// l0 stored as fp16 (__half2 stores); l1 accumulated fp32, stored fp16.
// ---------------------------------------------------------------------------
__global__ __launch_bounds__(256, 2) void gemm_hmma_kernel()
{
    __shared__ __align__(1024) unsigned char smem[24576];   // 3 x 8KB stages
    const uint32_t sbase = smem_u32(smem);

    const int tid  = threadIdx.x;
    const int lane = tid & 31;
    const int wid  = tid >> 5;
    const int nt = blockIdx.x, mt = blockIdx.y, b = blockIdx.z;
    const int warp_m = wid & 3, warp_n = wid >> 2;
    const int m0w = warp_m * 32, n0w = warp_n * 64;

    const int ck = tid >> 4;
    const int cg = tid & 15;
    const uint32_t cdst = ck * 256 + SWZ(cg, ck) * 16;
    const size_t gsrc_a = ((size_t)b * C_ + ck) * P_ + mt * 128 + cg * 8;
    const size_t gsrc_b = ((size_t)b * C_ + ck) * P_ + nt * 128 + cg * 8;

    auto prefetch = [&](int s, int c) {
        uint32_t st = sbase + s * 8192 + cdst;
        size_t koff = (size_t)c * 16 * P_;
        cp16(st +    0, gA + gsrc_a + koff);
        cp16(st + 4096, gB + gsrc_b + koff);
        cp_commit();
    };

    const int alk   = (lane & 7) | ((lane & 16) >> 1);
    const int amsel = (lane >> 3) & 1;
    const int bkrow = (lane & 7) | ((lane & 8));
    const int bngo  = (lane >> 4) & 1;

    float acc[2][8][4];
    #pragma unroll
    for (int i = 0; i < 2; i++)
        #pragma unroll
        for (int j = 0; j < 8; j++)
            #pragma unroll
            for (int q = 0; q < 4; q++) acc[i][j][q] = 0.0f;

    prefetch(0, 0);
    prefetch(1, 1);

    for (int c = 0; c < 16; c++) {
        if (c < 14) asm volatile("cp.async.wait_group 1;" ::: "memory");
        else        asm volatile("cp.async.wait_group 0;" ::: "memory");
        __syncthreads();
        if (c + 2 < 16) prefetch((c + 2) % 3, c + 2);

        uint32_t st = sbase + (c % 3) * 8192;

        uint32_t ah[2][4];
        #pragma unroll
        for (int i = 0; i < 2; i++) {
            int mg = (m0w >> 3) + i * 2 + amsel;
            ldsm4t(ah[i], st + alk * 256 + SWZ(mg, alk) * 16);
        }

        uint32_t bh[4][4];
        #pragma unroll
        for (int jp = 0; jp < 4; jp++) {
            int ng = (n0w >> 3) + jp * 2 + bngo;
            ldsm4t(bh[jp], st + 4096 + bkrow * 256 + SWZ(ng, bkrow) * 16);
        }

        #pragma unroll
        for (int i = 0; i < 2; i++)
            #pragma unroll
            for (int jp = 0; jp < 4; jp++)
                #pragma unroll
                for (int jq = 0; jq < 2; jq++)
                    mma16816(acc[i][jp * 2 + jq], ah[i], bh[jp] + jq * 2);
    }

    #pragma unroll
    for (int i = 0; i < 2; i++)
        #pragma unroll
        for (int j = 0; j < 8; j++)
            #pragma unroll
            for (int q = 0; q < 4; q++) acc[i][j][q] *= 0.0625f;

    const int qr = lane >> 2;
    const int qc = lane & 3;

    // l0 stores: fp16, one __half2 (4B) per row per j
    #pragma unroll
    for (int i = 0; i < 2; i++) {
        int m = mt * 128 + m0w + i * 16 + qr;
        size_t row0 = ((size_t)(b * P_ + m)) * P_;
        size_t row1 = ((size_t)(b * P_ + m + 8)) * P_;
        #pragma unroll
        for (int j = 0; j < 8; j++) {
            int nn = nt * 128 + n0w + j * 8 + qc * 2;
            *(__half2*)(g_l0 + row0 + nn) = __floats2half2_rn(acc[i][j][0], acc[i][j][1]);
            *(__half2*)(g_l0 + row1 + nn) = __floats2half2_rn(acc[i][j][2], acc[i][j][3]);
        }
    }

    // pool_l1: fp32 accumulation in smem, fp16 store
    __syncthreads();
    float* l1buf = (float*)smem;     // [128][33]
    if (warp_n == 0) {
        #pragma unroll
        for (int i = 0; i < 2; i++) {
            int mr = m0w + i * 16 + qr;
            #pragma unroll
            for (int j = 0; j < 8; j++) {
                int xp = j * 4 + qc;
                l1buf[mr * 33 + xp]       = acc[i][j][0] + acc[i][j][1];
                l1buf[(mr + 8) * 33 + xp] = acc[i][j][2] + acc[i][j][3];
            }
        }
    }
    __syncthreads();
    if (warp_n == 1) {
        #pragma unroll
        for (int i = 0; i < 2; i++) {
            int mr = m0w + i * 16 + qr;
            #pragma unroll
            for (int j = 0; j < 8; j++) {
                int xp = j * 4 + qc;
                l1buf[mr * 33 + xp]       += acc[i][j][0] + acc[i][j][1];
                l1buf[(mr + 8) * 33 + xp] += acc[i][j][2] + acc[i][j][3];
            }
        }
    }
    __syncthreads();
    {
        int m = tid >> 1, half = tid & 1;
        const float* sp = l1buf + m * 33 + half * 16;
        __half2 hv[8];
        #pragma unroll
        for (int q = 0; q < 8; q++)
            hv[q] = __floats2half2_rn(sp[2*q] * 0.25f, sp[2*q+1] * 0.25f);
        __half* dst = g_l1 + ((size_t)(b * P_ + mt * 128 + m)) * 1024 + nt * 32 + half * 16;
        *(uint4*)dst       = *(uint4*)&hv[0];
        *(uint4*)(dst + 8) = *(uint4*)&hv[4];
    }
}

// ---------------------------------------------------------------------------
// Kernel 2: fused pooling l1(fp16) -> l2(fp32) -> l3(fp32). One block per (b,p).
// ---------------------------------------------------------------------------
__global__ __launch_bounds__(256) void pool23_kernel()
{
    __shared__ float s1[1024];
    __shared__ float s2[256];
    const int bp = blockIdx.x;
    const int t = threadIdx.x;

    {
        uint2 r = *(const uint2*)(g_l1 + (size_t)bp * 1024 + t * 4);
        float2 a = __half22float2(*(__half2*)&r.x);
        float2 c = __half22float2(*(__half2*)&r.y);
        s1[t*4+0] = a.x; s1[t*4+1] = a.y; s1[t*4+2] = c.x; s1[t*4+3] = c.y;
    }
    __syncthreads();

    {
        int y = t >> 4, x = t & 15;
        const float* s = s1 + (2*y) * 32 + 2*x;
        float v = 0.25f * (s[0] + s[1] + s[32] + s[33]);
        s2[t] = v;
        g_l2[(size_t)bp * 256 + t] = v;
    }
    __syncthreads();

    if (t < 64) {
        int y = t >> 3, x = t & 7;
        const float* s = s2 + (2*y) * 16 + 2*x;
        g_l3[(size_t)bp * 64 + t] = 0.25f * (s[0] + s[1] + s[16] + s[17]);
    }
}

// ---------------------------------------------------------------------------
// Kernel 3: window gather + bilinear, all 4 levels per warp.
// l0/l1 read as fp16, l2/l3 as fp32; patch + math in fp32.
// ---------------------------------------------------------------------------
__global__ __launch_bounds__(256) void gather_kernel(
    const float* __restrict__ coords, float* __restrict__ out)
{
    __shared__ float patch_s[8][104];
    __shared__ __align__(16) float out_s[8][CTOT_];

    const int wl   = threadIdx.x >> 5;
    const int lane = threadIdx.x & 31;
    unsigned w = blockIdx.x * 8u + wl;   // (b,n,p)

    const int p = w & (P_ - 1); w >>= 12;
    const int n = w & 3;
    const int b = w >> 2;

    const float cx = coords[((size_t)((b * N_ + n) * 2 + 0)) * P_ + p];
    const float cy = coords[((size_t)((b * N_ + n) * 2 + 1)) * P_ + p];

    const int k1 = lane + 32, k2 = lane + 64;
    const int ix0 = lane / 9, iy0 = lane % 9;
    const int ix1 = k1 / 9,   iy1 = k1 % 9;
    const int ix2 = k2 / 9,   iy2 = k2 % 9;

    const int pj0 = lane / 10,      pi0 = lane % 10;
    const int pj1 = (lane+32) / 10, pi1 = (lane+32) % 10;
    const int pj2 = (lane+64) / 10, pi2 = (lane+64) % 10;
    const int pj3 = (lane+96) / 10, pi3 = (lane+96) % 10;

    float* pw = patch_s[wl];
    float* ow = out_s[wl];

    #pragma unroll
    for (int l = 0; l < 4; l++) {
        const int sz = 64 >> l;
        const float inv = 1.0f / (float)(1 << l);
        const __half* baseh = nullptr;
        const float*  basef = nullptr;
        if (l == 0)      baseh = g_l0 + (size_t)(b * P_ + p) * 4096;
        else if (l == 1) baseh = g_l1 + (size_t)(b * P_ + p) * 1024;
        else if (l == 2) basef = g_l2 + (size_t)(b * P_ + p) * 256;
        else             basef = g_l3 + (size_t)(b * P_ + p) * 64;

        const float xs = cx * inv;
        const float ys = cy * inv;
        const float x0f = floorf(xs);
        const float y0f = floorf(ys);
        const float fx = xs - x0f;
        const float fy = ys - y0f;
        const int x0 = (int)x0f;
        const int y0 = (int)y0f;

        auto fetch = [&](int j, int i) -> float {
            int yy = y0 - 4 + j, xx = x0 - 4 + i;
            if ((unsigned)yy < (unsigned)sz && (unsigned)xx < (unsigned)sz) {
                int off = yy * sz + xx;
                return (l < 2) ? __half2float(baseh[off]) : basef[off];
            }
            return 0.0f;
        };

        pw[lane]      = fetch(pj0, pi0);
        pw[lane + 32] = fetch(pj1, pi1);
        pw[lane + 64] = fetch(pj2, pi2);
        if (lane < 4) pw[lane + 96] = fetch(pj3, pi3);
        __syncwarp();

        const float w00 = (1.0f - fy) * (1.0f - fx);
        const float w01 = (1.0f - fy) * fx;
        const float w10 = fy * (1.0f - fx);
        const float w11 = fy * fx;
        float* ob = ow + l * K2_;

        {
            float v00 = pw[iy0*10 + ix0],     v01 = pw[iy0*10 + ix0 + 1];
            float v10 = pw[(iy0+1)*10 + ix0], v11 = pw[(iy0+1)*10 + ix0 + 1];
            ob[lane] = w00*v00 + w01*v01 + w10*v10 + w11*v11;
        }
        {
            float v00 = pw[iy1*10 + ix1],     v01 = pw[iy1*10 + ix1 + 1];
            float v10 = pw[(iy1+1)*10 + ix1], v11 = pw[(iy1+1)*10 + ix1 + 1];
            ob[k1] = w00*v00 + w01*v01 + w10*v10 + w11*v11;
        }
        if (k2 < K2_) {
            float v00 = pw[iy2*10 + ix2],     v01 = pw[iy2*10 + ix2 + 1];
            float v10 = pw[(iy2+1)*10 + ix2], v11 = pw[(iy2+1)*10 + ix2 + 1];
            ob[k2] = w00*v00 + w01*v01 + w10*v10 + w11*v11;
        }
        __syncwarp();
    }

    const float4* os = (const float4*)ow;
    float4* dst = (float4*)(out + ((size_t)((b * N_ + n) * P_ + p)) * CTOT_);
    dst[lane]      = os[lane];
    dst[lane + 32] = os[lane + 32];
    if (lane < 17) dst[lane + 64] = os[lane + 64];
}

// ---------------------------------------------------------------------------
extern "C" void kernel_launch(void* const* d_in, const int* in_sizes, int n_in,
                              void* d_out, int out_size)
{
    const float* f1     = (const float*)d_in[0];
    const float* f2     = (const float*)d_in[1];
    const float* coords = (const float*)d_in[2];
    float* out = (float*)d_out;

    // 0) fp32 -> fp16
    dim3 cgrid((B_ * C_ * P_) / (256 * 4), 2);
    convert_kernel<<<cgrid, 256>>>(f1, f2);

    // 1) HMMA fp16 correlation GEMM (+ fused pool_l1)
    dim3 gg(32, 32, 2);
    gemm_hmma_kernel<<<gg, 256>>>();

    // 2) fused pyramid tail (l2 + l3)
    pool23_kernel<<<B_ * P_, 256>>>();

    // 3) gather: one warp per (b,n,p)
    gather_kernel<<<(B_ * N_ * P_) / 8, 256>>>(coords, out);
}